// round 12
// baseline (speedup 1.0000x reference)
#include <cuda_runtime.h>
#include <cuda_bf16.h>
#include <cstdint>

// ===================== problem constants =====================
static constexpr int T_STEPS = 2048;
static constexpr int Bb = 256;    // batch
static constexpr int Hh = 512;    // hidden
static constexpr int HG = 32;     // hidden groups (16 hidden units each)
static constexpr int BG = 4;      // batch groups (64 batch each)
static constexpr int GRID = HG * BG;   // 128 CTAs
static constexpr int NTHR = 128;
static constexpr int MH = 16;     // hidden per CTA
static constexpr int NB = 64;     // batch per CTA
static constexpr int KCH = 128;   // K chunk size
static constexpr int NCH = Hh / KCH;  // 4 chunks

// ===================== SMEM layout =====================
static constexpr int OFF_X    = 0;                 // 64 f32
static constexpr int OFF_WIH  = 256;               // 64 f32
static constexpr int OFF_BIAS = 512;               // 64 f32
static constexpr int OFF_WHI  = 1024;              // 64 rows x 1024B = 65536
static constexpr int OFF_WLO  = OFF_WHI + 65536;   // 65536
static constexpr int H_ROWB   = KCH * 2 + 16;      // 272B padded row (bank-safe)
static constexpr int H_PLANE  = NB * H_ROWB;       // 17408
static constexpr int OFF_H    = OFF_WLO + 65536;   // [slot 0/1][plane hi/lo]
static constexpr int SMEM_ALLOC = OFF_H + 4 * H_PLANE;   // 201728 B

static constexpr unsigned SPIN_BOUND = 16u << 20;  // hang safety

// ===================== device scratch =====================
__device__ __align__(16) __nv_bfloat16 g_hhi[2][BG][NB][Hh];
__device__ __align__(16) __nv_bfloat16 g_hlo[2][BG][NB][Hh];
__device__ __align__(16) float         g_hlast[Bb * Hh];
__device__ unsigned int g_bar[BG];
__device__ unsigned int g_bar_exit[BG];

// ===================== helpers =====================
#define DINL __device__ __forceinline__

DINL uint32_t s2u(const void* p) {
    uint32_t a;
    asm("{ .reg .u64 t; cvta.to.shared.u64 t, %1; cvt.u32.u64 %0, t; }"
        : "=r"(a) : "l"(p));
    return a;
}

DINL void ldsm4(uint32_t* r, uint32_t addr) {
    asm volatile("ldmatrix.sync.aligned.m8n8.x4.shared.b16 {%0,%1,%2,%3}, [%4];"
                 : "=r"(r[0]), "=r"(r[1]), "=r"(r[2]), "=r"(r[3]) : "r"(addr));
}

DINL void mma16816(float* d, const uint32_t* a, uint32_t b0, uint32_t b1) {
    asm volatile(
        "mma.sync.aligned.m16n8k16.row.col.f32.bf16.bf16.f32 "
        "{%0,%1,%2,%3}, {%4,%5,%6,%7}, {%8,%9}, {%0,%1,%2,%3};"
        : "+f"(d[0]), "+f"(d[1]), "+f"(d[2]), "+f"(d[3])
        : "r"(a[0]), "r"(a[1]), "r"(a[2]), "r"(a[3]), "r"(b0), "r"(b1));
}

DINL void cp16(uint32_t dst, const void* src) {
    asm volatile("cp.async.cg.shared.global [%0], [%1], 16;" :: "r"(dst), "l"(src));
}
#define CP_COMMIT() asm volatile("cp.async.commit_group;" ::: "memory")
#define CP_WAIT0()  asm volatile("cp.async.wait_group 0;" ::: "memory")

DINL unsigned ld_acq(const unsigned* p) {
    unsigned v;
    asm volatile("ld.acquire.gpu.u32 %0, [%1];" : "=r"(v) : "l"(p) : "memory");
    return v;
}

DINL float fsig(float x) { float e = __expf(-x); return __fdividef(1.0f, 1.0f + e); }
DINL float ftanh_(float x) {
    float a = fabsf(x);
    float e = __expf(-2.0f * a);
    float t = __fdividef(1.0f - e, 1.0f + e);
    return copysignf(t, x);
}

DINL uint32_t pack_bf2(__nv_bfloat16 lo, __nv_bfloat16 hi) {
    return ((uint32_t)__bfloat16_as_ushort(hi) << 16) | (uint32_t)__bfloat16_as_ushort(lo);
}

// W SMEM address: row m (0..63), byte column kb (0..1023), XOR-16B row rotation
DINL uint32_t w_off(int m, uint32_t kb) {
    return (uint32_t)m * 1024u + (kb ^ ((uint32_t)(m & 7) * 16u));
}

// ===================== main persistent LSTM kernel =====================
__global__ void __launch_bounds__(NTHR, 1)
lstm_kernel(const float* __restrict__ x,      // (T, B)
            const float* __restrict__ W_ih,   // (4H, 1)
            const float* __restrict__ W_hh,   // (4H, H)
            const float* __restrict__ b_ih,   // (4H)
            const float* __restrict__ b_hh)   // (4H)
{
    extern __shared__ __align__(16) char smp[];
    const uint32_t sb = s2u(smp);

    const int tid = threadIdx.x;
    const int w   = tid >> 5;
    const int l   = tid & 31;
    const int hg  = blockIdx.x & (HG - 1);   // hidden group (16 units)
    const int bg  = blockIdx.x >> 5;         // batch group (64 rows)

    float* xs  = (float*)(smp + OFF_X);
    float* wih = (float*)(smp + OFF_WIH);
    float* bia = (float*)(smp + OFF_BIAS);

    // ---- prologue: split W_hh rows into bf16 hi/lo planes in SMEM ----
    {
        const int m  = tid >> 1;             // local row 0..63 (gate*16 + j)
        const int kh = (tid & 1) * 256;
        const int r  = (m >> 4) * Hh + hg * MH + (m & 15);
        const float* wr = W_hh + (size_t)r * Hh;
        for (int k = kh; k < kh + 256; k += 2) {
            float f0 = wr[k], f1 = wr[k + 1];
            __nv_bfloat16 h0 = __float2bfloat16(f0);
            __nv_bfloat16 h1 = __float2bfloat16(f1);
            __nv_bfloat16 l0 = __float2bfloat16(f0 - __bfloat162float(h0));
            __nv_bfloat16 l1 = __float2bfloat16(f1 - __bfloat162float(h1));
            uint32_t off = w_off(m, (uint32_t)k * 2u);
            *(uint32_t*)(smp + OFF_WHI + off) = pack_bf2(h0, h1);
            *(uint32_t*)(smp + OFF_WLO + off) = pack_bf2(l0, l1);
        }
    }
    if (tid < 64) {
        int r = (tid >> 4) * Hh + hg * MH + (tid & 15);
        wih[tid] = W_ih[r];
        bia[tid] = b_ih[r] + b_hh[r];
    }

    // ---- zero h(-1) (buffer 1) for our produced slice ----
#pragma unroll
    for (int it = 0; it < 16; it++) {
        int idx = it * NTHR + tid;           // 2048 items: 2 planes x 64b x 16j
        int plane = idx >> 10, rem = idx & 1023;
        int b = rem >> 4, j = rem & 15;
        if (plane == 0) g_hhi[1][bg][b][hg * MH + j] = __float2bfloat16(0.0f);
        else            g_hlo[1][bg][b][hg * MH + j] = __float2bfloat16(0.0f);
    }
    __threadfence();
    __syncthreads();
    if (tid == 0) atomicAdd(&g_bar[bg], 1u);

    // ---- per-thread fragment geometry ----
    const int j0 = l >> 2;          // C-frag rows within 16-hidden tile
    const int wb = w * 16;          // warp's batch base
    const int bc = wb + 2 * (l & 3);
    // per-(gate, jrow) input-proj consts
    float wihr[4][2], biar[4][2];
#pragma unroll
    for (int g = 0; g < 4; g++) {
        wihr[g][0] = wih[g * 16 + j0];     biar[g][0] = bia[g * 16 + j0];
        wihr[g][1] = wih[g * 16 + j0 + 8]; biar[g][1] = bia[g * 16 + j0 + 8];
    }
    // ldmatrix per-thread A addressing
    const int arow = l & 15;
    const uint32_t acsel = (uint32_t)(l >> 4) * 16u;
    const uint32_t asw = (uint32_t)(arow & 7) * 16u;
    const uint32_t arow_base = (uint32_t)arow * 1024u;

    float creg[2][4];               // cell state: [frag(b/b+8)][e]
#pragma unroll
    for (int f = 0; f < 2; f++)
#pragma unroll
        for (int e = 0; e < 4; e++) creg[f][e] = 0.0f;

    unsigned bail = 0;

    for (int t = 0; t < T_STEPS; t++) {
        // ---- wait for h(t-1) from all 32 CTAs of this batch group ----
        if (tid == 0 && !bail) {
            unsigned target = 32u * (unsigned)(t + 1);
            unsigned tries = 0;
            while (ld_acq(&g_bar[bg]) < target)
                if (++tries > SPIN_BOUND) { bail = 1; break; }
        }
        __syncthreads();

        if (tid < 64) xs[tid] = x[(size_t)t * Bb + bg * NB + tid];

        const int rb = (t + 1) & 1;
        const __nv_bfloat16* hip = &g_hhi[rb][bg][0][0];
        const __nv_bfloat16* lop = &g_hlo[rb][bg][0][0];

        // issue chunk 0 into slot 0
        {
            const int c = 0;
#pragma unroll
            for (int it = 0; it < 16; it++) {
                int idx = it * NTHR + tid;
                int plane = idx >> 10, rem = idx & 1023;
                int n = rem >> 4, six = rem & 15;
                const char* src = (const char*)(plane ? lop : hip)
                                + ((size_t)n * Hh + c * KCH) * 2 + six * 16;
                uint32_t dst = sb + OFF_H + (uint32_t)plane * H_PLANE
                             + (uint32_t)n * H_ROWB + (uint32_t)six * 16u;
                cp16(dst, src);
            }
            CP_COMMIT();
        }

        float acc[4][2][4];
#pragma unroll
        for (int g = 0; g < 4; g++)
#pragma unroll
            for (int f = 0; f < 2; f++)
#pragma unroll
                for (int e = 0; e < 4; e++) acc[g][f][e] = 0.0f;

        for (int c = 0; c < NCH; c++) {
            CP_WAIT0();
            __syncthreads();   // chunk c resident for all threads

            // prefetch chunk c+1 into the other slot (safe: all threads done with it)
            if (c < NCH - 1) {
                const int cn = c + 1;
                const uint32_t slot = (uint32_t)(cn & 1) * 2u * H_PLANE;
#pragma unroll
                for (int it = 0; it < 16; it++) {
                    int idx = it * NTHR + tid;
                    int plane = idx >> 10, rem = idx & 1023;
                    int n = rem >> 4, six = rem & 15;
                    const char* src = (const char*)(plane ? lop : hip)
                                    + ((size_t)n * Hh + cn * KCH) * 2 + six * 16;
                    uint32_t dst = sb + OFF_H + slot + (uint32_t)plane * H_PLANE
                                 + (uint32_t)n * H_ROWB + (uint32_t)six * 16u;
                    cp16(dst, src);
                }
                CP_COMMIT();
            }

            const uint32_t hbase = sb + OFF_H + (uint32_t)(c & 1) * 2u * H_PLANE;
            const uint32_t lbase = hbase + H_PLANE;
            const uint32_t kcb = (uint32_t)c * 256u;   // chunk base byte col in W

#pragma unroll
            for (int ks = 0; ks < 8; ks++) {
                const uint32_t kb = kcb + (uint32_t)ks * 32u;  // global byte col
                // A fragments (Whi, Wlo) for 4 gates
                uint32_t ahi[4][4], alo[4][4];
#pragma unroll
                for (int g = 0; g < 4; g++) {
                    uint32_t off = (uint32_t)g * 16384u + arow_base
                                 + (((kb | acsel)) ^ asw);
                    ldsm4(ahi[g], sb + OFF_WHI + off);
                    ldsm4(alo[g], sb + OFF_WLO + off);
                }
                // B fragments: hhi/hlo, n8-frags at warp_n+0 and +8
                const uint32_t brow0 = (uint32_t)(wb + (l >> 2)) * H_ROWB
                                     + (uint32_t)(ks * 16 + 2 * (l & 3)) * 2u;
                const uint32_t brow1 = brow0 + 8u * H_ROWB;
                uint32_t bh0a = *(const uint32_t*)(smp + (hbase - sb) + brow0);
                uint32_t bh0b = *(const uint32_t*)(smp + (hbase - sb) + brow0 + 16);
                uint32_t bh1a = *(const uint32_t*)(smp + (hbase - sb) + brow1);
                uint32_t bh1b = *(const uint32_t*)(smp + (hbase - sb) + brow1 + 16);
                uint32_t bl0a = *(const uint32_t*)(smp + (lbase - sb) + brow0);
                uint32_t bl0b = *(const uint32_t*)(smp + (lbase - sb) + brow0 + 16);
                uint32_t bl1a = *(const uint32_t*)(smp + (lbase - sb) + brow1);
                uint32_t bl1b = *(const uint32_t*)(smp + (lbase - sb) + brow1 + 16);
#pragma unroll
                for (int g = 0; g < 4; g++) {
                    mma16816(acc[g][0], ahi[g], bh0a, bh0b);  // Whi*hhi
                    mma16816(acc[g][1], ahi[g], bh1a, bh1b);
                    mma16816(acc[g][0], ahi[g], bl0a, bl0b);  // Whi*hlo
                    mma16816(acc[g][1], ahi[g], bl1a, bl1b);
                    mma16816(acc[g][0], alo[g], bh0a, bh0b);  // Wlo*hhi
                    mma16816(acc[g][1], alo[g], bh1a, bh1b);
                }
            }
        }

        // ---- epilogue: activations, cell update, h writeback ----
        {
            __nv_bfloat16* whp = &g_hhi[t & 1][bg][0][0];
            __nv_bfloat16* wlp = &g_hlo[t & 1][bg][0][0];
#pragma unroll
            for (int f = 0; f < 2; f++) {
#pragma unroll
                for (int e = 0; e < 4; e++) {
                    const int jr = e >> 1;                  // 0: j0, 1: j0+8
                    const int j  = j0 + jr * 8;
                    const int b  = bc + (e & 1) + f * 8;
                    const float xb = xs[b];
                    float gi = acc[0][f][e] + xb * wihr[0][jr] + biar[0][jr];
                    float gf = acc[1][f][e] + xb * wihr[1][jr] + biar[1][jr];
                    float gg = acc[2][f][e] + xb * wihr[2][jr] + biar[2][jr];
                    float go = acc[3][f][e] + xb * wihr[3][jr] + biar[3][jr];
                    float iv = fsig(gi);
                    float fv = fsig(gf);
                    float gv = ftanh_(gg);
                    float ov = fsig(go);
                    float cc = fv * creg[f][e] + iv * gv;
                    creg[f][e] = cc;
                    float hv = ov * ftanh_(cc);
                    __nv_bfloat16 hh = __float2bfloat16(hv);
                    __nv_bfloat16 hl = __float2bfloat16(hv - __bfloat162float(hh));
                    whp[(size_t)b * Hh + hg * MH + j] = hh;
                    wlp[(size_t)b * Hh + hg * MH + j] = hl;
                    if (t == T_STEPS - 1)
                        g_hlast[(size_t)(bg * NB + b) * Hh + hg * MH + j] = hv;
                }
            }
        }
        __threadfence();
        __syncthreads();
        if (tid == 0 && t < T_STEPS - 1) atomicAdd(&g_bar[bg], 1u);
    }

    // ---- reset barrier counters for deterministic graph replay ----
    __threadfence();
    __syncthreads();
    if (tid == 0) {
        atomicAdd(&g_bar_exit[bg], 1u);
        if (hg == 0) {
            unsigned tries = 0;
            while (ld_acq(&g_bar_exit[bg]) < 32u)
                if (++tries > SPIN_BOUND) break;
            atomicExch(&g_bar[bg], 0u);
            atomicExch(&g_bar_exit[bg], 0u);
        }
    }
}

// ===================== output projection: out[b] = h_last[b,:] . W_lin + b_lin
__global__ void __launch_bounds__(256)
proj_kernel(const float* __restrict__ W_lin, const float* __restrict__ b_lin,
            float* __restrict__ out)
{
    const int warp = (blockIdx.x * blockDim.x + threadIdx.x) >> 5;
    const int l = threadIdx.x & 31;
    if (warp >= Bb) return;
    const float* hr = g_hlast + (size_t)warp * Hh;
    float s = 0.0f;
#pragma unroll
    for (int k = l; k < Hh; k += 32) s += hr[k] * W_lin[k];
#pragma unroll
    for (int off = 16; off > 0; off >>= 1) s += __shfl_xor_sync(0xFFFFFFFFu, s, off);
    if (l == 0) out[warp] = s + b_lin[0];
}

// ===================== launch =====================
extern "C" void kernel_launch(void* const* d_in, const int* in_sizes, int n_in,
                              void* d_out, int out_size)
{
    const float* x     = (const float*)d_in[0];
    const float* W_ih  = (const float*)d_in[1];
    const float* W_hh  = (const float*)d_in[2];
    const float* b_ih  = (const float*)d_in[3];
    const float* b_hh  = (const float*)d_in[4];
    const float* W_lin = (const float*)d_in[5];
    const float* b_lin = (const float*)d_in[6];
    float* out = (float*)d_out;

    cudaFuncSetAttribute(lstm_kernel, cudaFuncAttributeMaxDynamicSharedMemorySize, SMEM_ALLOC);

    lstm_kernel<<<GRID, NTHR, SMEM_ALLOC>>>(x, W_ih, W_hh, b_ih, b_hh);
    proj_kernel<<<(Bb * 32 + 255) / 256, 256>>>(W_lin, b_lin, out);
}

// round 16
// speedup vs baseline: 1.4362x; 1.4362x over previous
#include <cuda_runtime.h>
#include <cuda_fp16.h>
#include <cstdint>

// ===================== problem constants =====================
static constexpr int T_STEPS = 2048;
static constexpr int Bb = 256;    // batch
static constexpr int Hh = 512;    // hidden
static constexpr int HG = 32;     // hidden groups (16 hidden units each)
static constexpr int BG = 4;      // batch groups (64 batch each)
static constexpr int GRID = HG * BG;   // 128 CTAs
static constexpr int NTHR = 128;
static constexpr int MH = 16;     // hidden per CTA
static constexpr int NB = 64;     // batch per CTA
static constexpr int KCH = 128;   // K chunk size
static constexpr int NCH = Hh / KCH;  // 4 chunks

// ===================== SMEM layout =====================
static constexpr int OFF_X    = 0;                 // 64 f32
static constexpr int OFF_WIH  = 256;               // 64 f32
static constexpr int OFF_BIAS = 512;               // 64 f32
static constexpr int GST_PITCH = 70;               // f32 pitch (bank-spread, 8B-align)
static constexpr int OFF_GST  = 1024;              // 64 rows x 70 f32 = 17920
static constexpr int OFF_WHI  = 19456;             // 64 rows x 1024B = 65536
static constexpr int OFF_WLO  = OFF_WHI + 65536;
static constexpr int H_ROWB   = KCH * 2 + 16;      // 272B padded row
static constexpr int HSLOT    = NB * H_ROWB;       // 17408
static constexpr int OFF_H    = OFF_WLO + 65536;   // 2 slots
static constexpr int SMEM_ALLOC = OFF_H + 2 * HSLOT;   // 185344 B

static constexpr unsigned SPIN_BOUND = 16u << 20;  // hang safety

// ===================== device scratch =====================
__device__ __align__(16) __half g_h[2][BG][NB][Hh];
__device__ __align__(16) float  g_hlast[Bb * Hh];
__device__ unsigned int g_bar[BG];
__device__ unsigned int g_bar_exit[BG];

// ===================== helpers =====================
#define DINL __device__ __forceinline__

DINL uint32_t s2u(const void* p) {
    uint32_t a;
    asm("{ .reg .u64 t; cvta.to.shared.u64 t, %1; cvt.u32.u64 %0, t; }"
        : "=r"(a) : "l"(p));
    return a;
}

DINL void ldsm4(uint32_t* r, uint32_t addr) {
    asm volatile("ldmatrix.sync.aligned.m8n8.x4.shared.b16 {%0,%1,%2,%3}, [%4];"
                 : "=r"(r[0]), "=r"(r[1]), "=r"(r[2]), "=r"(r[3]) : "r"(addr));
}

DINL void mma16816(float* d, const uint32_t* a, uint32_t b0, uint32_t b1) {
    asm volatile(
        "mma.sync.aligned.m16n8k16.row.col.f32.f16.f16.f32 "
        "{%0,%1,%2,%3}, {%4,%5,%6,%7}, {%8,%9}, {%0,%1,%2,%3};"
        : "+f"(d[0]), "+f"(d[1]), "+f"(d[2]), "+f"(d[3])
        : "r"(a[0]), "r"(a[1]), "r"(a[2]), "r"(a[3]), "r"(b0), "r"(b1));
}

DINL void cp16(uint32_t dst, const void* src) {
    asm volatile("cp.async.cg.shared.global [%0], [%1], 16;" :: "r"(dst), "l"(src));
}
#define CP_COMMIT() asm volatile("cp.async.commit_group;" ::: "memory")
#define CP_WAIT0()  asm volatile("cp.async.wait_group 0;" ::: "memory")

DINL unsigned ld_acq(const unsigned* p) {
    unsigned v;
    asm volatile("ld.acquire.gpu.u32 %0, [%1];" : "=r"(v) : "l"(p) : "memory");
    return v;
}

DINL float fsig(float x) { float e = __expf(-x); return __fdividef(1.0f, 1.0f + e); }
DINL float ftanh_(float x) {
    float a = fabsf(x);
    float e = __expf(-2.0f * a);
    float t = __fdividef(1.0f - e, 1.0f + e);
    return copysignf(t, x);
}

DINL uint32_t pack_h2(__half lo, __half hi) {
    return ((uint32_t)__half_as_ushort(hi) << 16) | (uint32_t)__half_as_ushort(lo);
}

// W SMEM: row m (0..63), byte column kb (0..1023), XOR-16B row rotation
DINL uint32_t w_off(int m, uint32_t kb) {
    return (uint32_t)m * 1024u + (kb ^ ((uint32_t)(m & 7) * 16u));
}

// ===================== main persistent LSTM kernel =====================
__global__ void __launch_bounds__(NTHR, 1)
lstm_kernel(const float* __restrict__ x,      // (T, B)
            const float* __restrict__ W_ih,   // (4H, 1)
            const float* __restrict__ W_hh,   // (4H, H)
            const float* __restrict__ b_ih,   // (4H)
            const float* __restrict__ b_hh)   // (4H)
{
    extern __shared__ __align__(16) char smp[];
    const uint32_t sb = s2u(smp);

    const int tid = threadIdx.x;
    const int w   = tid >> 5;      // warp = gate
    const int l   = tid & 31;
    const int hg  = blockIdx.x & (HG - 1);
    const int bg  = blockIdx.x >> 5;

    float* xs  = (float*)(smp + OFF_X);
    float* wih = (float*)(smp + OFF_WIH);
    float* bia = (float*)(smp + OFF_BIAS);
    float* stg = (float*)(smp + OFF_GST);

    // ---- prologue: split W_hh rows into fp16 hi/lo planes in SMEM ----
    {
        const int m  = tid >> 1;             // local row 0..63 (gate*16 + j)
        const int kh = (tid & 1) * 256;
        const int r  = (m >> 4) * Hh + hg * MH + (m & 15);
        const float* wr = W_hh + (size_t)r * Hh;
        for (int k = kh; k < kh + 256; k += 2) {
            float f0 = wr[k], f1 = wr[k + 1];
            __half h0 = __float2half_rn(f0);
            __half h1 = __float2half_rn(f1);
            __half l0 = __float2half_rn(f0 - __half2float(h0));
            __half l1 = __float2half_rn(f1 - __half2float(h1));
            uint32_t off = w_off(m, (uint32_t)k * 2u);
            *(uint32_t*)(smp + OFF_WHI + off) = pack_h2(h0, h1);
            *(uint32_t*)(smp + OFF_WLO + off) = pack_h2(l0, l1);
        }
    }
    if (tid < 64) {
        int r = (tid >> 4) * Hh + hg * MH + (tid & 15);
        wih[tid] = W_ih[r];
        bia[tid] = b_ih[r] + b_hh[r];
    }

    // ---- zero h(-1) (buffer 1) for our produced slice ----
    {
        const int b0 = tid >> 1, jh0 = tid & 1;
        *(uint4*)&g_h[1][bg][b0][hg * MH + jh0 * 8] = make_uint4(0, 0, 0, 0);
    }
    __threadfence();
    __syncthreads();
    if (tid == 0) atomicAdd(&g_bar[bg], 1u);

    // ---- fragment geometry ----
    const int j0 = l >> 2;                                   // C-frag row
    const uint32_t arow_base = (uint32_t)(w * MH + (l & 15)) * 1024u;
    const uint32_t asw   = (uint32_t)(l & 7) * 16u;
    const uint32_t acsel = (uint32_t)(l >> 4) * 16u;
    const uint32_t bofs0 = (uint32_t)(4 * (l & 3));          // B-frag byte col base
    const int eb  = tid >> 1;        // epilogue: batch row
    const int ejh = tid & 1;         // epilogue: j half (0..7 / 8..15)

    float creg[8];
#pragma unroll
    for (int q = 0; q < 8; q++) creg[q] = 0.0f;

    unsigned bail = 0;

    for (int t = 0; t < T_STEPS; t++) {
        // ---- wait for h(t-1) from all 32 CTAs of this batch group ----
        if (tid == 0 && !bail) {
            unsigned target = 32u * (unsigned)(t + 1);
            unsigned tries = 0;
            while (ld_acq(&g_bar[bg]) < target)
                if (++tries > SPIN_BOUND) { bail = 1; break; }
        }
        __syncthreads();

        if (tid < 64) xs[tid] = x[(size_t)t * Bb + bg * NB + tid];

        const int rb = (t + 1) & 1;
        const char* hp = (const char*)&g_h[rb][bg][0][0];

        // issue chunk 0 into slot 0  (16KB: 1024 x 16B)
#pragma unroll
        for (int it = 0; it < 8; it++) {
            int idx = it * NTHR + tid;
            int n = idx >> 4, six = idx & 15;
            cp16(sb + OFF_H + (uint32_t)n * H_ROWB + (uint32_t)six * 16u,
                 hp + ((size_t)n * Hh) * 2 + six * 16);
        }
        CP_COMMIT();

        float acc[8][4];
#pragma unroll
        for (int nf = 0; nf < 8; nf++)
#pragma unroll
            for (int e = 0; e < 4; e++) acc[nf][e] = 0.0f;

        for (int c = 0; c < NCH; c++) {
            CP_WAIT0();
            __syncthreads();   // chunk c resident

            if (c < NCH - 1) {             // prefetch chunk c+1
                const int cn = c + 1;
                const uint32_t slot = (uint32_t)(cn & 1) * HSLOT;
#pragma unroll
                for (int it = 0; it < 8; it++) {
                    int idx = it * NTHR + tid;
                    int n = idx >> 4, six = idx & 15;
                    cp16(sb + OFF_H + slot + (uint32_t)n * H_ROWB + (uint32_t)six * 16u,
                         hp + ((size_t)n * Hh + cn * KCH) * 2 + six * 16);
                }
                CP_COMMIT();
            }

            const char* hb = smp + OFF_H + (c & 1) * HSLOT;

#pragma unroll
            for (int ks = 0; ks < 8; ks++) {
                const uint32_t kb = (uint32_t)(c * 8 + ks) * 32u;   // global byte col in W
                uint32_t ahi[4], alo[4];
                const uint32_t aoff = arow_base + ((kb | acsel) ^ asw);
                ldsm4(ahi, sb + OFF_WHI + aoff);
                ldsm4(alo, sb + OFF_WLO + aoff);

                const uint32_t bcol = (uint32_t)(ks * 32) + bofs0;  // byte col in chunk
#pragma unroll
                for (int nf = 0; nf < 8; nf++) {
                    const char* bp = hb + (uint32_t)(nf * 8 + j0) * H_ROWB + bcol;
                    uint32_t b0 = *(const uint32_t*)bp;
                    uint32_t b1 = *(const uint32_t*)(bp + 16);
                    mma16816(acc[nf], ahi, b0, b1);   // Whi * h
                    mma16816(acc[nf], alo, b0, b1);   // Wlo * h
                }
            }
        }

        // ---- stage gates to SMEM: stg[(gate*16 + j)*70 + b] ----
#pragma unroll
        for (int nf = 0; nf < 8; nf++) {
            float* d0 = stg + (uint32_t)(w * MH + j0) * GST_PITCH + nf * 8 + 2 * (l & 3);
            *(float2*)d0 = make_float2(acc[nf][0], acc[nf][1]);
            float* d1 = d0 + 8 * GST_PITCH;
            *(float2*)d1 = make_float2(acc[nf][2], acc[nf][3]);
        }
        __syncthreads();

        // ---- epilogue: thread = (batch eb, j-half ejh), 8 j each ----
        {
            const float xb = xs[eb];
            uint32_t hpack[4];
            ushort hus[8];
#pragma unroll
            for (int jj = 0; jj < 8; jj++) {
                const int j = ejh * 8 + jj;
                float gi = stg[(0 * 16 + j) * GST_PITCH + eb] + xb * wih[0 * 16 + j] + bia[0 * 16 + j];
                float gf = stg[(1 * 16 + j) * GST_PITCH + eb] + xb * wih[1 * 16 + j] + bia[1 * 16 + j];
                float gg = stg[(2 * 16 + j) * GST_PITCH + eb] + xb * wih[2 * 16 + j] + bia[2 * 16 + j];
                float go = stg[(3 * 16 + j) * GST_PITCH + eb] + xb * wih[3 * 16 + j] + bia[3 * 16 + j];
                float iv = fsig(gi);
                float fv = fsig(gf);
                float gv = ftanh_(gg);
                float ov = fsig(go);
                float cc = fv * creg[jj] + iv * gv;
                creg[jj] = cc;
                float hv = ov * ftanh_(cc);
                hus[jj] = __half_as_ushort(__float2half_rn(hv));
                if (t == T_STEPS - 1)
                    g_hlast[(size_t)(bg * NB + eb) * Hh + hg * MH + j] = hv;
            }
#pragma unroll
            for (int q = 0; q < 4; q++)
                hpack[q] = (uint32_t)hus[2 * q] | ((uint32_t)hus[2 * q + 1] << 16);
            *(uint4*)&g_h[t & 1][bg][eb][hg * MH + ejh * 8] =
                make_uint4(hpack[0], hpack[1], hpack[2], hpack[3]);
        }
        __threadfence();
        __syncthreads();
        if (tid == 0 && t < T_STEPS - 1) atomicAdd(&g_bar[bg], 1u);
    }

    // ---- reset barrier counters for deterministic graph replay ----
    __threadfence();
    __syncthreads();
    if (tid == 0) {
        atomicAdd(&g_bar_exit[bg], 1u);
        if (hg == 0) {
            unsigned tries = 0;
            while (ld_acq(&g_bar_exit[bg]) < 32u)
                if (++tries > SPIN_BOUND) break;
            atomicExch(&g_bar[bg], 0u);
            atomicExch(&g_bar_exit[bg], 0u);
        }
    }
}

// ===================== output projection: out[b] = h_last[b,:] . W_lin + b_lin
__global__ void __launch_bounds__(256)
proj_kernel(const float* __restrict__ W_lin, const float* __restrict__ b_lin,
            float* __restrict__ out)
{
    const int warp = (blockIdx.x * blockDim.x + threadIdx.x) >> 5;
    const int l = threadIdx.x & 31;
    if (warp >= Bb) return;
    const float* hr = g_hlast + (size_t)warp * Hh;
    float s = 0.0f;
#pragma unroll
    for (int k = l; k < Hh; k += 32) s += hr[k] * W_lin[k];
#pragma unroll
    for (int off = 16; off > 0; off >>= 1) s += __shfl_xor_sync(0xFFFFFFFFu, s, off);
    if (l == 0) out[warp] = s + b_lin[0];
}

// ===================== launch =====================
extern "C" void kernel_launch(void* const* d_in, const int* in_sizes, int n_in,
                              void* d_out, int out_size)
{
    const float* x     = (const float*)d_in[0];
    const float* W_ih  = (const float*)d_in[1];
    const float* W_hh  = (const float*)d_in[2];
    const float* b_ih  = (const float*)d_in[3];
    const float* b_hh  = (const float*)d_in[4];
    const float* W_lin = (const float*)d_in[5];
    const float* b_lin = (const float*)d_in[6];
    float* out = (float*)d_out;

    cudaFuncSetAttribute(lstm_kernel, cudaFuncAttributeMaxDynamicSharedMemorySize, SMEM_ALLOC);

    lstm_kernel<<<GRID, NTHR, SMEM_ALLOC>>>(x, W_ih, W_hh, b_ih, b_hh);
    proj_kernel<<<(Bb * 32 + 255) / 256, 256>>>(W_lin, b_lin, out);
}

// round 17
// speedup vs baseline: 1.8727x; 1.3040x over previous
#include <cuda_runtime.h>
#include <cuda_fp16.h>
#include <cstdint>

// ===================== problem constants =====================
static constexpr int T_STEPS = 2048;
static constexpr int Bb = 256;    // batch
static constexpr int Hh = 512;    // hidden
static constexpr int HG = 32;     // hidden groups (16 hidden units each)
static constexpr int BG = 4;      // batch groups (64 batch each)
static constexpr int GRID = HG * BG;   // 128 CTAs
static constexpr int NTHR = 128;
static constexpr int MH = 16;     // hidden per CTA
static constexpr int NB = 64;     // batch per CTA
static constexpr int KCH = 128;   // K chunk size
static constexpr int NCH = Hh / KCH;  // 4 chunks

// ===================== SMEM layout =====================
static constexpr int OFF_X    = 0;                 // 64 f32
static constexpr int OFF_WIH  = 256;               // 64 f32
static constexpr int OFF_BIAS = 512;               // 64 f32
static constexpr int GST_PITCH = 70;               // f32 pitch (bank-spread, 8B-align)
static constexpr int OFF_GST  = 1024;              // 64 rows x 70 f32 = 17920
static constexpr int OFF_WHI  = 19456;             // 64 rows x 1024B = 65536
static constexpr int H_ROWB   = KCH * 2 + 16;      // 272B padded row
static constexpr int HSLOT    = NB * H_ROWB;       // 17408
static constexpr int OFF_H    = OFF_WHI + 65536;   // 4 slots (one per chunk)
static constexpr int SMEM_ALLOC = OFF_H + NCH * HSLOT;   // 154624 B

static constexpr unsigned SPIN_BOUND = 16u << 20;  // hang safety

// ===================== device scratch =====================
__device__ __align__(16) __half g_h[2][BG][NB][Hh];
__device__ __align__(16) float  g_hlast[Bb * Hh];
__device__ unsigned int g_bar[BG];
__device__ unsigned int g_bar_exit[BG];

// ===================== helpers =====================
#define DINL __device__ __forceinline__

DINL uint32_t s2u(const void* p) {
    uint32_t a;
    asm("{ .reg .u64 t; cvta.to.shared.u64 t, %1; cvt.u32.u64 %0, t; }"
        : "=r"(a) : "l"(p));
    return a;
}

DINL void ldsm4(uint32_t* r, uint32_t addr) {
    asm volatile("ldmatrix.sync.aligned.m8n8.x4.shared.b16 {%0,%1,%2,%3}, [%4];"
                 : "=r"(r[0]), "=r"(r[1]), "=r"(r[2]), "=r"(r[3]) : "r"(addr));
}

DINL void mma16816(float* d, const uint32_t* a, uint32_t b0, uint32_t b1) {
    asm volatile(
        "mma.sync.aligned.m16n8k16.row.col.f32.f16.f16.f32 "
        "{%0,%1,%2,%3}, {%4,%5,%6,%7}, {%8,%9}, {%0,%1,%2,%3};"
        : "+f"(d[0]), "+f"(d[1]), "+f"(d[2]), "+f"(d[3])
        : "r"(a[0]), "r"(a[1]), "r"(a[2]), "r"(a[3]), "r"(b0), "r"(b1));
}

DINL void cp16(uint32_t dst, const void* src) {
    asm volatile("cp.async.cg.shared.global [%0], [%1], 16;" :: "r"(dst), "l"(src));
}
#define CP_COMMIT() asm volatile("cp.async.commit_group;" ::: "memory")

DINL unsigned ld_acq(const unsigned* p) {
    unsigned v;
    asm volatile("ld.acquire.gpu.u32 %0, [%1];" : "=r"(v) : "l"(p) : "memory");
    return v;
}

DINL float fsig(float x) { float e = __expf(-x); return __fdividef(1.0f, 1.0f + e); }
DINL float ftanh_(float x) {
    float a = fabsf(x);
    float e = __expf(-2.0f * a);
    float t = __fdividef(1.0f - e, 1.0f + e);
    return copysignf(t, x);
}

DINL uint32_t pack_h2(__half lo, __half hi) {
    return ((uint32_t)__half_as_ushort(hi) << 16) | (uint32_t)__half_as_ushort(lo);
}

// W SMEM: row m (0..63), byte column kb (0..1023), XOR-16B row rotation
DINL uint32_t w_off(int m, uint32_t kb) {
    return (uint32_t)m * 1024u + (kb ^ ((uint32_t)(m & 7) * 16u));
}

// ===================== main persistent LSTM kernel =====================
__global__ void __launch_bounds__(NTHR, 1)
lstm_kernel(const float* __restrict__ x,      // (T, B)
            const float* __restrict__ W_ih,   // (4H, 1)
            const float* __restrict__ W_hh,   // (4H, H)
            const float* __restrict__ b_ih,   // (4H)
            const float* __restrict__ b_hh)   // (4H)
{
    extern __shared__ __align__(16) char smp[];
    const uint32_t sb = s2u(smp);

    const int tid = threadIdx.x;
    const int w   = tid >> 5;      // warp = gate
    const int l   = tid & 31;
    const int hg  = blockIdx.x & (HG - 1);
    const int bg  = blockIdx.x >> 5;

    float* xs  = (float*)(smp + OFF_X);
    float* wih = (float*)(smp + OFF_WIH);
    float* bia = (float*)(smp + OFF_BIAS);
    float* stg = (float*)(smp + OFF_GST);

    // ---- prologue: W_hh -> fp16 plane in SMEM ----
    {
        const int m  = tid >> 1;             // local row 0..63 (gate*16 + j)
        const int kh = (tid & 1) * 256;
        const int r  = (m >> 4) * Hh + hg * MH + (m & 15);
        const float* wr = W_hh + (size_t)r * Hh;
        for (int k = kh; k < kh + 256; k += 2) {
            __half h0 = __float2half_rn(wr[k]);
            __half h1 = __float2half_rn(wr[k + 1]);
            *(uint32_t*)(smp + OFF_WHI + w_off(m, (uint32_t)k * 2u)) = pack_h2(h0, h1);
        }
    }
    if (tid < 64) {
        int r = (tid >> 4) * Hh + hg * MH + (tid & 15);
        wih[tid] = W_ih[r];
        bia[tid] = b_ih[r] + b_hh[r];
    }

    // ---- zero h(-1) (buffer 1) for our produced slice ----
    {
        const int b0 = tid >> 1, jh0 = tid & 1;
        *(uint4*)&g_h[1][bg][b0][hg * MH + jh0 * 8] = make_uint4(0, 0, 0, 0);
    }
    __threadfence();
    __syncthreads();
    if (tid == 0) atomicAdd(&g_bar[bg], 1u);

    // ---- fragment geometry ----
    const int j0 = l >> 2;                                   // C-frag row
    const uint32_t arow_base = (uint32_t)(w * MH + (l & 15)) * 1024u;
    const uint32_t asw   = (uint32_t)(l & 7) * 16u;
    const uint32_t acsel = (uint32_t)(l >> 4) * 16u;
    // B ldsm per-thread row/col offset within a chunk slot:
    //  tiles: 0:(n+0,k+0) 1:(n+0,k+16B) 2:(n+8,k+0) 3:(n+8,k+16B)
    const uint32_t bofs = ((uint32_t)((l >> 4) & 1) * 8u + (uint32_t)(l & 7)) * (uint32_t)H_ROWB
                        + (uint32_t)((l >> 3) & 1) * 16u;
    const int eb  = tid >> 1;        // epilogue: batch row
    const int ejh = tid & 1;         // epilogue: j half

    float creg[8];
#pragma unroll
    for (int q = 0; q < 8; q++) creg[q] = 0.0f;

    unsigned bail = 0;

    for (int t = 0; t < T_STEPS; t++) {
        // ---- wait for h(t-1) from all 32 CTAs of this batch group ----
        if (tid == 0 && !bail) {
            unsigned target = 32u * (unsigned)(t + 1);
            unsigned tries = 0;
            while (ld_acq(&g_bar[bg]) < target)
                if (++tries > SPIN_BOUND) { bail = 1; break; }
        }
        __syncthreads();

        if (tid < 64) xs[tid] = x[(size_t)t * Bb + bg * NB + tid];

        const int rb = (t + 1) & 1;
        const char* hp = (const char*)&g_h[rb][bg][0][0];

        // ---- issue ALL chunk loads up-front (4 commit groups) ----
#pragma unroll
        for (int c = 0; c < NCH; c++) {
#pragma unroll
            for (int it = 0; it < 8; it++) {
                int idx = it * NTHR + tid;
                int n = idx >> 4, six = idx & 15;
                cp16(sb + OFF_H + (uint32_t)c * HSLOT
                         + (uint32_t)n * H_ROWB + (uint32_t)six * 16u,
                     hp + ((size_t)n * Hh + c * KCH) * 2 + six * 16);
            }
            CP_COMMIT();
        }

        float acc[8][4];
#pragma unroll
        for (int nf = 0; nf < 8; nf++)
#pragma unroll
            for (int e = 0; e < 4; e++) acc[nf][e] = 0.0f;

#pragma unroll
        for (int c = 0; c < NCH; c++) {
            switch (c) {   // wait: chunk c complete when <= NCH-1-c groups pending
                case 0: asm volatile("cp.async.wait_group 3;" ::: "memory"); break;
                case 1: asm volatile("cp.async.wait_group 2;" ::: "memory"); break;
                case 2: asm volatile("cp.async.wait_group 1;" ::: "memory"); break;
                default: asm volatile("cp.async.wait_group 0;" ::: "memory"); break;
            }
            __syncthreads();   // chunk c resident for all threads

            const uint32_t hb = sb + OFF_H + (uint32_t)c * HSLOT + bofs;

#pragma unroll
            for (int ks = 0; ks < 8; ks++) {
                const uint32_t kb = (uint32_t)(c * 8 + ks) * 32u;   // byte col in W
                uint32_t a[4];
                ldsm4(a, sb + OFF_WHI + arow_base + ((kb | acsel) ^ asw));

                const uint32_t bcol = hb + (uint32_t)(ks * 32);
#pragma unroll
                for (int p = 0; p < 4; p++) {
                    uint32_t bf[4];
                    ldsm4(bf, bcol + (uint32_t)p * 16u * (uint32_t)H_ROWB);
                    mma16816(acc[2 * p],     a, bf[0], bf[1]);
                    mma16816(acc[2 * p + 1], a, bf[2], bf[3]);
                }
            }
        }

        // ---- stage gates to SMEM: stg[(gate*16 + j)*70 + b] ----
#pragma unroll
        for (int nf = 0; nf < 8; nf++) {
            float* d0 = stg + (uint32_t)(w * MH + j0) * GST_PITCH + nf * 8 + 2 * (l & 3);
            *(float2*)d0 = make_float2(acc[nf][0], acc[nf][1]);
            float* d1 = d0 + 8 * GST_PITCH;
            *(float2*)d1 = make_float2(acc[nf][2], acc[nf][3]);
        }
        __syncthreads();

        // ---- epilogue: thread = (batch eb, j-half ejh), 8 j each ----
        {
            const float xb = xs[eb];
            uint32_t hpack[4];
            ushort hus[8];
#pragma unroll
            for (int jj = 0; jj < 8; jj++) {
                const int j = ejh * 8 + jj;
                float gi = stg[(0 * 16 + j) * GST_PITCH + eb] + xb * wih[0 * 16 + j] + bia[0 * 16 + j];
                float gf = stg[(1 * 16 + j) * GST_PITCH + eb] + xb * wih[1 * 16 + j] + bia[1 * 16 + j];
                float gg = stg[(2 * 16 + j) * GST_PITCH + eb] + xb * wih[2 * 16 + j] + bia[2 * 16 + j];
                float go = stg[(3 * 16 + j) * GST_PITCH + eb] + xb * wih[3 * 16 + j] + bia[3 * 16 + j];
                float iv = fsig(gi);
                float fv = fsig(gf);
                float gv = ftanh_(gg);
                float ov = fsig(go);
                float cc = fv * creg[jj] + iv * gv;
                creg[jj] = cc;
                float hv = ov * ftanh_(cc);
                hus[jj] = __half_as_ushort(__float2half_rn(hv));
                if (t == T_STEPS - 1)
                    g_hlast[(size_t)(bg * NB + eb) * Hh + hg * MH + j] = hv;
            }
#pragma unroll
            for (int q = 0; q < 4; q++)
                hpack[q] = (uint32_t)hus[2 * q] | ((uint32_t)hus[2 * q + 1] << 16);
            *(uint4*)&g_h[t & 1][bg][eb][hg * MH + ejh * 8] =
                make_uint4(hpack[0], hpack[1], hpack[2], hpack[3]);
        }
        __threadfence();
        __syncthreads();
        if (tid == 0 && t < T_STEPS - 1) atomicAdd(&g_bar[bg], 1u);
    }

    // ---- reset barrier counters for deterministic graph replay ----
    __threadfence();
    __syncthreads();
    if (tid == 0) {
        atomicAdd(&g_bar_exit[bg], 1u);
        if (hg == 0) {
            unsigned tries = 0;
            while (ld_acq(&g_bar_exit[bg]) < 32u)
                if (++tries > SPIN_BOUND) break;
            atomicExch(&g_bar[bg], 0u);
            atomicExch(&g_bar_exit[bg], 0u);
        }
    }
}

// ===================== output projection: out[b] = h_last[b,:] . W_lin + b_lin
__global__ void __launch_bounds__(256)
proj_kernel(const float* __restrict__ W_lin, const float* __restrict__ b_lin,
            float* __restrict__ out)
{
    const int warp = (blockIdx.x * blockDim.x + threadIdx.x) >> 5;
    const int l = threadIdx.x & 31;
    if (warp >= Bb) return;
    const float* hr = g_hlast + (size_t)warp * Hh;
    float s = 0.0f;
#pragma unroll
    for (int k = l; k < Hh; k += 32) s += hr[k] * W_lin[k];
#pragma unroll
    for (int off = 16; off > 0; off >>= 1) s += __shfl_xor_sync(0xFFFFFFFFu, s, off);
    if (l == 0) out[warp] = s + b_lin[0];
}

// ===================== launch =====================
extern "C" void kernel_launch(void* const* d_in, const int* in_sizes, int n_in,
                              void* d_out, int out_size)
{
    const float* x     = (const float*)d_in[0];
    const float* W_ih  = (const float*)d_in[1];
    const float* W_hh  = (const float*)d_in[2];
    const float* b_ih  = (const float*)d_in[3];
    const float* b_hh  = (const float*)d_in[4];
    const float* W_lin = (const float*)d_in[5];
    const float* b_lin = (const float*)d_in[6];
    float* out = (float*)d_out;

    cudaFuncSetAttribute(lstm_kernel, cudaFuncAttributeMaxDynamicSharedMemorySize, SMEM_ALLOC);

    lstm_kernel<<<GRID, NTHR, SMEM_ALLOC>>>(x, W_ih, W_hh, b_ih, b_hh);
    proj_kernel<<<(Bb * 32 + 255) / 256, 256>>>(W_lin, b_lin, out);
}